// round 6
// baseline (speedup 1.0000x reference)
#include <cuda_runtime.h>
#include <cuda_bf16.h>

// Problem constants
#define NB   2
#define NPTS 8192
#define NS   1024
#define NK   16
#define NC   29

// Output layout (concatenated flattened reference returns, float32):
// new_xyz  (2,3,1024)    -> [0, 6144)
// new_points (2,128,1024)-> [6144, 268288)
// fps_idx  (2,1024)      -> [268288, 270336)
#define OUT_NP  6144
#define OUT_FPS 268288

// Scratch (static device globals; no allocation allowed)
__device__ int   g_fps[NB * NS];
__device__ float g_newxyz[NB * 3 * NS];
__device__ int   g_knn[NB * NS * NK];

// ---------------------------------------------------------------------------
// Kernel 1: Farthest point sampling. One CTA per batch, 1024 threads,
// 8 points per thread in registers. Packed 64-bit argmax key gives
// first-occurrence tie semantics. Non-contracted math (XLA fusion
// semantics) — verified bit-exact in R2/R3/R4.
// ---------------------------------------------------------------------------
__global__ void __launch_bounds__(1024) fps_kernel(const float* __restrict__ xyz,
                                                   float* __restrict__ out)
{
    const int b   = blockIdx.x;
    const int tid = threadIdx.x;
    const float* X = xyz + b * 3 * NPTS;

    float px[8], py[8], pz[8], dd[8];
#pragma unroll
    for (int p = 0; p < 8; p++) {
        int n = tid + p * 1024;
        px[p] = X[n];
        py[p] = X[NPTS + n];
        pz[p] = X[2 * NPTS + n];
        dd[p] = 1e10f;
    }

    __shared__ unsigned long long wmax[32];
    __shared__ int sf;

    int f = 0;
    for (int s = 0; s < NS; s++) {
        float cx = X[f];
        float cy = X[NPTS + f];
        float cz = X[2 * NPTS + f];

        if (tid == 0) {
            g_fps[b * NS + s] = f;
            out[OUT_FPS + b * NS + s] = (float)f;
            g_newxyz[b * 3072 + s]        = cx;
            g_newxyz[b * 3072 + 1024 + s] = cy;
            g_newxyz[b * 3072 + 2048 + s] = cz;
            out[b * 3072 + s]        = cx;
            out[b * 3072 + 1024 + s] = cy;
            out[b * 3072 + 2048 + s] = cz;
        }

        unsigned long long best = 0ull;
#pragma unroll
        for (int p = 0; p < 8; p++) {
            float dx = __fsub_rn(px[p], cx);
            float dy = __fsub_rn(py[p], cy);
            float dz = __fsub_rn(pz[p], cz);
            float d  = __fadd_rn(__fadd_rn(__fmul_rn(dx, dx), __fmul_rn(dy, dy)),
                                 __fmul_rn(dz, dz));
            dd[p] = fminf(dd[p], d);
            unsigned long long key =
                ((unsigned long long)__float_as_uint(dd[p]) << 32) |
                (unsigned)(8191 - (tid + p * 1024));
            best = (key > best) ? key : best;
        }
#pragma unroll
        for (int o = 16; o > 0; o >>= 1) {
            unsigned long long v = __shfl_xor_sync(0xffffffffu, best, o);
            best = (v > best) ? v : best;
        }
        if ((tid & 31) == 0) wmax[tid >> 5] = best;
        __syncthreads();
        if (tid < 32) {
            unsigned long long v = wmax[tid];
#pragma unroll
            for (int o = 16; o > 0; o >>= 1) {
                unsigned long long u = __shfl_xor_sync(0xffffffffu, v, o);
                v = (u > v) ? u : v;
            }
            if (tid == 0) sf = 8191 - (int)(v & 0xffffffffu);
        }
        __syncthreads();
        f = sf;
    }
}

// ---------------------------------------------------------------------------
// Kernel 2: KNN among the 1024 sampled points. Numerics model:
//   sq   = XLA elementwise/reduce fusion -> non-contracted mul/add chain
//   dot  = cublas SGEMM K-loop           -> FFMA chain:
//          dot = fma(z_i,z_j, fma(y_i,y_j, x_i*x_j))
//   d2   = XLA fusion: (sq_i + sq_j) - 2*dot, non-contracted.
// 16-slot sorted insertion, strict-greater shift => stable tie-break
// (lower index first) like jax.lax.top_k.
// ---------------------------------------------------------------------------
__global__ void __launch_bounds__(128) knn_kernel()
{
    __shared__ float snx[3072];
    const int b = blockIdx.x >> 3;                    // 16 blocks: 8 per batch
    const int s = (blockIdx.x & 7) * 128 + threadIdx.x;

    for (int t = threadIdx.x; t < 3072; t += 128)
        snx[t] = g_newxyz[b * 3072 + t];
    __syncthreads();

    const float xi = snx[s], yi = snx[1024 + s], zi = snx[2048 + s];
    const float sqi = __fadd_rn(__fadd_rn(__fmul_rn(xi, xi), __fmul_rn(yi, yi)),
                                __fmul_rn(zi, zi));

    float bd[16];
    int   bi[16];
#pragma unroll
    for (int k = 0; k < 16; k++) { bd[k] = 3.4e38f; bi[k] = 0; }

    for (int j = 0; j < NS; j++) {
        float xj = snx[j], yj = snx[1024 + j], zj = snx[2048 + j];
        float sqj = __fadd_rn(__fadd_rn(__fmul_rn(xj, xj), __fmul_rn(yj, yj)),
                              __fmul_rn(zj, zj));
        // cublas-style FFMA accumulation over c = 0,1,2
        float dot = __fmaf_rn(zi, zj, __fmaf_rn(yi, yj, __fmul_rn(xi, xj)));
        float d2  = __fsub_rn(__fadd_rn(sqi, sqj), __fmul_rn(2.0f, dot));
        if (d2 < bd[15]) {
            int p = 15;
            while (p > 0 && bd[p - 1] > d2) {
                bd[p] = bd[p - 1];
                bi[p] = bi[p - 1];
                p--;
            }
            bd[p] = d2;
            bi[p] = j;
        }
    }

    const int base = (b * NS + s) * NK;
    for (int k = 0; k < 16; k++) g_knn[base + k] = bi[k];
}

// ---------------------------------------------------------------------------
// Kernel 3: fused build (fg -> outer -> squeeze) + conv0..conv3 + relu,
// one CTA per sample (b,s). Plain fp32 (reference convs are exact fp32;
// accumulation-order noise ~1e-6 is well under threshold).
//
// Shared layout (floats):
//   fg 512 | x0 16384 | ws 4608 | y0 2304 | y1 1024 | y2 512 = 25344
// ---------------------------------------------------------------------------
#define SMEM_FLOATS 25344

__global__ void __launch_bounds__(192) fused_conv_kernel(
    const float* __restrict__ feats,
    const float* __restrict__ w0, const float* __restrict__ w1,
    const float* __restrict__ w2, const float* __restrict__ w3,
    float* __restrict__ out)
{
    extern __shared__ float sm[];
    float* fg = sm;             // 512
    float* x0 = sm + 512;       // 16384
    float* ws = x0 + 16384;     // 4608
    float* y0 = ws + 4608;      // 2304
    float* y1 = y0 + 2304;      // 1024
    float* y2 = y1 + 1024;      // 512

    const int sid = blockIdx.x;
    const int b   = sid >> 10;
    const int s   = sid & 1023;
    const int tid = threadIdx.x;

    // --- Phase A: fg[d][k] ---------------------------------------------
    for (int t = tid; t < 512; t += 192) {
        int d = t >> 4, k = t & 15;
        int j = g_knn[sid * NK + k];
        float v;
        if (d < 3)
            v = g_newxyz[b * 3072 + d * 1024 + j] - g_newxyz[b * 3072 + d * 1024 + s];
        else
            v = feats[(b * NC + (d - 3)) * NPTS + j];
        fg[t] = v;
    }
    __syncthreads();

    // --- Phase B: build squeezed conv0 input ----------------------------
    for (int t = tid; t < 16384; t += 192) {
        int oc = t >> 6, pix = t & 63;
        int y = pix >> 3, x = pix & 7;
        int q = oc >> 6, c = oc & 63;
        float v = 1.0f;
        if (c < 32) {
            int i = 2 * y + (int)(q == 1 || q == 3);
            int j = 2 * x + (int)(q == 1 || q == 2);
            v = fg[c * 16 + i] * fg[c * 16 + j];
        }
        x0[t] = v;
    }

    // --- conv0: 256ch 8x8 -> 64ch 6x6 ----------------------------------
    const int oy = tid % 6;
    const int og = tid / 6;   // 0..31, oc = 2*og, 2*og+1
    float a0[6], a1[6];
#pragma unroll
    for (int i = 0; i < 6; i++) { a0[i] = 0.f; a1[i] = 0.f; }

    for (int ch = 0; ch < 32; ch++) {
        const int ic0 = ch * 8;
        __syncthreads();                 // protect ws from previous readers
        for (int t = tid; t < 4608; t += 192) {
            int icc = t / 576, rem = t % 576;
            int oc = rem / 9, k = rem % 9;
            ws[t] = w0[oc * 2304 + (ic0 + icc) * 9 + k];
        }
        __syncthreads();
        for (int icc = 0; icc < 8; icc++) {
            const float* xs = x0 + ((ic0 + icc) << 6);
            float xr[3][8];
#pragma unroll
            for (int r = 0; r < 3; r++)
#pragma unroll
                for (int c = 0; c < 8; c++)
                    xr[r][c] = xs[(oy + r) * 8 + c];
            const float* wp = ws + icc * 576 + og * 18;
#pragma unroll
            for (int ky = 0; ky < 3; ky++)
#pragma unroll
                for (int kx = 0; kx < 3; kx++) {
                    float wa = wp[ky * 3 + kx];
                    float wb = wp[9 + ky * 3 + kx];
#pragma unroll
                    for (int ox = 0; ox < 6; ox++) {
                        a0[ox] += xr[ky][ox + kx] * wa;
                        a1[ox] += xr[ky][ox + kx] * wb;
                    }
                }
        }
    }
    {
        int oc = og * 2;
#pragma unroll
        for (int ox = 0; ox < 6; ox++) {
            y0[oc * 36 + oy * 6 + ox]       = fmaxf(a0[ox], 0.f);
            y0[(oc + 1) * 36 + oy * 6 + ox] = fmaxf(a1[ox], 0.f);
        }
    }

    // --- conv1: 64ch 6x6 -> 64ch 4x4 ------------------------------------
    const int oy1 = tid % 4;
    const int og1 = tid / 4;  // valid for tid<128
    float b0[4], b1[4];
#pragma unroll
    for (int i = 0; i < 4; i++) { b0[i] = 0.f; b1[i] = 0.f; }

    for (int ch = 0; ch < 8; ch++) {
        const int ic0 = ch * 8;
        __syncthreads();
        for (int t = tid; t < 4608; t += 192) {
            int icc = t / 576, rem = t % 576;
            int oc = rem / 9, k = rem % 9;
            ws[t] = w1[oc * 576 + (ic0 + icc) * 9 + k];
        }
        __syncthreads();
        if (tid < 128) {
            for (int icc = 0; icc < 8; icc++) {
                const float* xs = y0 + (ic0 + icc) * 36;
                float xr[3][6];
#pragma unroll
                for (int r = 0; r < 3; r++)
#pragma unroll
                    for (int c = 0; c < 6; c++)
                        xr[r][c] = xs[(oy1 + r) * 6 + c];
                const float* wp = ws + icc * 576 + og1 * 18;
#pragma unroll
                for (int ky = 0; ky < 3; ky++)
#pragma unroll
                    for (int kx = 0; kx < 3; kx++) {
                        float wa = wp[ky * 3 + kx];
                        float wb = wp[9 + ky * 3 + kx];
#pragma unroll
                        for (int ox = 0; ox < 4; ox++) {
                            b0[ox] += xr[ky][ox + kx] * wa;
                            b1[ox] += xr[ky][ox + kx] * wb;
                        }
                    }
            }
        }
    }
    if (tid < 128) {
        int oc = og1 * 2;
#pragma unroll
        for (int ox = 0; ox < 4; ox++) {
            y1[oc * 16 + oy1 * 4 + ox]       = fmaxf(b0[ox], 0.f);
            y1[(oc + 1) * 16 + oy1 * 4 + ox] = fmaxf(b1[ox], 0.f);
        }
    }

    // --- conv2: 64ch 4x4 -> 128ch 2x2 -----------------------------------
    float c2[4] = {0.f, 0.f, 0.f, 0.f};
    for (int ch = 0; ch < 16; ch++) {
        const int ic0 = ch * 4;
        __syncthreads();
        for (int t = tid; t < 4608; t += 192) {
            int icc = t / 1152, rem = t % 1152;
            int oc = rem / 9, k = rem % 9;
            ws[t] = w2[oc * 576 + (ic0 + icc) * 9 + k];
        }
        __syncthreads();
        if (tid < 128) {
            for (int icc = 0; icc < 4; icc++) {
                const float* xs = y1 + (ic0 + icc) * 16;
                float xr[16];
#pragma unroll
                for (int p = 0; p < 16; p++) xr[p] = xs[p];
                const float* wp = ws + icc * 1152 + tid * 9;
#pragma unroll
                for (int ky = 0; ky < 3; ky++)
#pragma unroll
                    for (int kx = 0; kx < 3; kx++) {
                        float wv = wp[ky * 3 + kx];
#pragma unroll
                        for (int oy2 = 0; oy2 < 2; oy2++)
#pragma unroll
                            for (int ox2 = 0; ox2 < 2; ox2++)
                                c2[oy2 * 2 + ox2] += xr[(oy2 + ky) * 4 + ox2 + kx] * wv;
                    }
            }
        }
    }
    if (tid < 128) {
#pragma unroll
        for (int p = 0; p < 4; p++) y2[tid * 4 + p] = fmaxf(c2[p], 0.f);
    }

    // --- conv3: 128ch 2x2 -> 128ch 1x1 ----------------------------------
    float acc3 = 0.f;
    for (int ch = 0; ch < 16; ch++) {
        const int ic0 = ch * 8;
        __syncthreads();
        for (int t = tid; t < 4096; t += 192) {
            int icc = t >> 9, rem = t & 511;
            int oc = rem >> 2, k = rem & 3;
            ws[t] = w3[oc * 512 + (ic0 + icc) * 4 + k];
        }
        __syncthreads();
        if (tid < 128) {
            for (int icc = 0; icc < 8; icc++) {
                const float* xs = y2 + (ic0 + icc) * 4;
                const float* wp = ws + icc * 512 + tid * 4;
                acc3 += xs[0] * wp[0] + xs[1] * wp[1] + xs[2] * wp[2] + xs[3] * wp[3];
            }
        }
    }
    if (tid < 128) {
        out[OUT_NP + b * 131072 + tid * 1024 + s] = fmaxf(acc3, 0.f);
    }
}

// ---------------------------------------------------------------------------
extern "C" void kernel_launch(void* const* d_in, const int* in_sizes, int n_in,
                              void* d_out, int out_size)
{
    const float* xyz   = (const float*)d_in[0];
    const float* feats = (const float*)d_in[1];
    const float* w0    = (const float*)d_in[2];
    const float* w1    = (const float*)d_in[3];
    const float* w2    = (const float*)d_in[4];
    const float* w3    = (const float*)d_in[5];
    float* out = (float*)d_out;

    cudaFuncSetAttribute(fused_conv_kernel,
                         cudaFuncAttributeMaxDynamicSharedMemorySize,
                         SMEM_FLOATS * (int)sizeof(float));

    fps_kernel<<<NB, 1024>>>(xyz, out);
    knn_kernel<<<16, 128>>>();
    fused_conv_kernel<<<NB * NS, 192, SMEM_FLOATS * sizeof(float)>>>(
        feats, w0, w1, w2, w3, out);
}

// round 11
// speedup vs baseline: 1.2084x; 1.2084x over previous
#include <cuda_runtime.h>
#include <cuda_bf16.h>

// Problem constants
#define NB   2
#define NPTS 8192
#define NS   1024
#define NK   16
#define NC   29

// Output layout (concatenated flattened reference returns, float32):
// new_xyz  (2,3,1024)    -> [0, 6144)
// new_points (2,128,1024)-> [6144, 268288)
// fps_idx  (2,1024)      -> [268288, 270336)
#define OUT_NP  6144
#define OUT_FPS 268288

// Scratch (static device globals; no allocation allowed)
__device__ int   g_fps[NB * NS];
__device__ float g_newxyz[NB * 3 * NS];
__device__ int   g_knn[NB * NS * NK];

// ---- packed f32x2 helpers (Blackwell; ptxas won't auto-fuse, PTX only) ----
__device__ __forceinline__ unsigned long long pk2(float lo, float hi)
{
    unsigned long long r;
    asm("mov.b64 %0, {%1,%2};" : "=l"(r) : "f"(lo), "f"(hi));
    return r;
}
__device__ __forceinline__ unsigned long long fma2(unsigned long long a,
                                                   unsigned long long b,
                                                   unsigned long long c)
{
    unsigned long long d;
    asm("fma.rn.f32x2 %0, %1, %2, %3;" : "=l"(d) : "l"(a), "l"(b), "l"(c));
    return d;
}
__device__ __forceinline__ void upk2(unsigned long long v, float& lo, float& hi)
{
    asm("mov.b64 {%0,%1}, %2;" : "=f"(lo), "=f"(hi) : "l"(v));
}

// ---------------------------------------------------------------------------
// Kernel 1: Farthest point sampling. One CTA per batch, 1024 threads,
// 8 points/thread in registers. Packed key (distbits<<32)|(8191-idx) keeps
// exact first-occurrence argmax. Reduction via REDUX (__reduce_max_sync):
// stage 1 warp-level, leaders -> parity double-buffered shared, ONE barrier,
// stage 2 redundantly in every warp => uniform f, no broadcast/2nd barrier.
// Distance math: non-contracted, reference association order (bit-exact
// validated R2-R6).
// ---------------------------------------------------------------------------
__global__ void __launch_bounds__(1024) fps_kernel(const float* __restrict__ xyz,
                                                   float* __restrict__ out)
{
    const int b    = blockIdx.x;
    const int tid  = threadIdx.x;
    const int lane = tid & 31;
    const int warp = tid >> 5;
    const float* X = xyz + b * 3 * NPTS;

    float px[8], py[8], pz[8], dd[8];
#pragma unroll
    for (int p = 0; p < 8; p++) {
        int n = tid + p * 1024;
        px[p] = X[n];
        py[p] = X[NPTS + n];
        pz[p] = X[2 * NPTS + n];
        dd[p] = 1e10f;
    }

    __shared__ unsigned long long wmax[2][32];

    int f = 0;
    for (int s = 0; s < NS; s++) {
        float cx = X[f];
        float cy = X[NPTS + f];
        float cz = X[2 * NPTS + f];

        if (tid == 0) {
            g_fps[b * NS + s] = f;
            out[OUT_FPS + b * NS + s] = (float)f;
            g_newxyz[b * 3072 + s]        = cx;
            g_newxyz[b * 3072 + 1024 + s] = cy;
            g_newxyz[b * 3072 + 2048 + s] = cz;
            out[b * 3072 + s]        = cx;
            out[b * 3072 + 1024 + s] = cy;
            out[b * 3072 + 2048 + s] = cz;
        }

        unsigned long long best = 0ull;
#pragma unroll
        for (int p = 0; p < 8; p++) {
            float dx = __fsub_rn(px[p], cx);
            float dy = __fsub_rn(py[p], cy);
            float dz = __fsub_rn(pz[p], cz);
            float d  = __fadd_rn(__fadd_rn(__fmul_rn(dx, dx), __fmul_rn(dy, dy)),
                                 __fmul_rn(dz, dz));
            dd[p] = fminf(dd[p], d);
            unsigned long long key =
                ((unsigned long long)__float_as_uint(dd[p]) << 32) |
                (unsigned)(8191 - (tid + p * 1024));
            best = (key > best) ? key : best;
        }

        // warp argmax via two REDUX ops (dist first, then masked idx-key)
        unsigned hi = (unsigned)(best >> 32);
        unsigned lo = (unsigned)best;
        unsigned whi = __reduce_max_sync(0xffffffffu, hi);
        unsigned wlo = __reduce_max_sync(0xffffffffu, (hi == whi) ? lo : 0u);
        if (lane == 0)
            wmax[s & 1][warp] = ((unsigned long long)whi << 32) | wlo;
        __syncthreads();

        // every warp reduces the 32 leader keys -> uniform f
        unsigned long long v = wmax[s & 1][lane];
        unsigned h2 = (unsigned)(v >> 32);
        unsigned l2 = (unsigned)v;
        unsigned fh = __reduce_max_sync(0xffffffffu, h2);
        unsigned fl = __reduce_max_sync(0xffffffffu, (h2 == fh) ? l2 : 0u);
        f = 8191 - (int)fl;
    }
}

// ---------------------------------------------------------------------------
// Kernel 2: KNN among the 1024 sampled points. Numerics (validated R6):
//   sq  : non-contracted mul/add chain (XLA fusion)
//   dot : cublas FFMA chain fma(z, z, fma(y, y, x*x))
//   d2  : (sq_i + sq_j) - 2*dot, non-contracted.
// ---------------------------------------------------------------------------
__global__ void __launch_bounds__(128) knn_kernel()
{
    __shared__ float snx[3072];
    const int b = blockIdx.x >> 3;                    // 16 blocks: 8 per batch
    const int s = (blockIdx.x & 7) * 128 + threadIdx.x;

    for (int t = threadIdx.x; t < 3072; t += 128)
        snx[t] = g_newxyz[b * 3072 + t];
    __syncthreads();

    const float xi = snx[s], yi = snx[1024 + s], zi = snx[2048 + s];
    const float sqi = __fadd_rn(__fadd_rn(__fmul_rn(xi, xi), __fmul_rn(yi, yi)),
                                __fmul_rn(zi, zi));

    float bd[16];
    int   bi[16];
#pragma unroll
    for (int k = 0; k < 16; k++) { bd[k] = 3.4e38f; bi[k] = 0; }

    for (int j = 0; j < NS; j++) {
        float xj = snx[j], yj = snx[1024 + j], zj = snx[2048 + j];
        float sqj = __fadd_rn(__fadd_rn(__fmul_rn(xj, xj), __fmul_rn(yj, yj)),
                              __fmul_rn(zj, zj));
        float dot = __fmaf_rn(zi, zj, __fmaf_rn(yi, yj, __fmul_rn(xi, xj)));
        float d2  = __fsub_rn(__fadd_rn(sqi, sqj), __fmul_rn(2.0f, dot));
        if (d2 < bd[15]) {
            int p = 15;
            while (p > 0 && bd[p - 1] > d2) {
                bd[p] = bd[p - 1];
                bi[p] = bi[p - 1];
                p--;
            }
            bd[p] = d2;
            bi[p] = j;
        }
    }

    const int base = (b * NS + s) * NK;
    for (int k = 0; k < 16; k++) g_knn[base + k] = bi[k];
}

// ---------------------------------------------------------------------------
// Kernel 3: fused build + conv0..conv3 + relu, one CTA per sample.
// conv0/conv1 use packed fma.rn.f32x2 over the oc-pair each thread owns:
// weights staged as (w[2og][k], w[2og+1][k]) 8-byte pairs -> one LDS.64 is
// a ready f32x2 operand; activations broadcast-packed once per reuse.
// Each f32x2 lane is an IEEE fp32 FMA == previous scalar FFMA: bit-exact.
//
// Shared layout (floats):
//   fg 512 | x0 16384 | ws 4608 | y0 2304 | y1 1024 | y2 512 = 25344
// ---------------------------------------------------------------------------
#define SMEM_FLOATS 25344

__global__ void __launch_bounds__(192) fused_conv_kernel(
    const float* __restrict__ feats,
    const float* __restrict__ w0, const float* __restrict__ w1,
    const float* __restrict__ w2, const float* __restrict__ w3,
    float* __restrict__ out)
{
    extern __shared__ float sm[];
    float* fg = sm;             // 512
    float* x0 = sm + 512;       // 16384
    float* ws = x0 + 16384;     // 4608   (8B-aligned: offset 16896 floats)
    float* y0 = ws + 4608;      // 2304
    float* y1 = y0 + 2304;      // 1024
    float* y2 = y1 + 1024;      // 512
    unsigned long long* ws2 = reinterpret_cast<unsigned long long*>(ws);

    const int sid = blockIdx.x;
    const int b   = sid >> 10;
    const int s   = sid & 1023;
    const int tid = threadIdx.x;

    // --- Phase A: fg[d][k] ---------------------------------------------
    for (int t = tid; t < 512; t += 192) {
        int d = t >> 4, k = t & 15;
        int j = g_knn[sid * NK + k];
        float v;
        if (d < 3)
            v = g_newxyz[b * 3072 + d * 1024 + j] - g_newxyz[b * 3072 + d * 1024 + s];
        else
            v = feats[(b * NC + (d - 3)) * NPTS + j];
        fg[t] = v;
    }
    __syncthreads();

    // --- Phase B: build squeezed conv0 input ----------------------------
    for (int t = tid; t < 16384; t += 192) {
        int oc = t >> 6, pix = t & 63;
        int y = pix >> 3, x = pix & 7;
        int q = oc >> 6, c = oc & 63;
        float v = 1.0f;
        if (c < 32) {
            int i = 2 * y + (int)(q == 1 || q == 3);
            int j = 2 * x + (int)(q == 1 || q == 2);
            v = fg[c * 16 + i] * fg[c * 16 + j];
        }
        x0[t] = v;
    }

    // --- conv0: 256ch 8x8 -> 64ch 6x6 (f32x2 over oc pair) --------------
    const int oy = tid % 6;
    const int og = tid / 6;   // 0..31, oc = 2*og, 2*og+1
    unsigned long long acc2[6];
#pragma unroll
    for (int i = 0; i < 6; i++) acc2[i] = 0ull;

    for (int ch = 0; ch < 32; ch++) {
        const int ic0 = ch * 8;
        __syncthreads();                 // protect ws from previous readers
        // stage pairs: ws2[(icc*32+og)*9 + k] = (w0[2og][ic][k], w0[2og+1][ic][k])
        for (int t = tid; t < 2304; t += 192) {
            int k = t % 9, rest = t / 9;
            int ogs = rest % 32, icc = rest / 32;
            int ic  = ic0 + icc;
            float wa = w0[(2 * ogs)     * 2304 + ic * 9 + k];
            float wb = w0[(2 * ogs + 1) * 2304 + ic * 9 + k];
            ws2[t] = pk2(wa, wb);
        }
        __syncthreads();
        for (int icc = 0; icc < 8; icc++) {
            const float* xs = x0 + ((ic0 + icc) << 6);
            unsigned long long xp[3][8];
#pragma unroll
            for (int r = 0; r < 3; r++) {
                const float4 v0 = *reinterpret_cast<const float4*>(xs + (oy + r) * 8);
                const float4 v1 = *reinterpret_cast<const float4*>(xs + (oy + r) * 8 + 4);
                xp[r][0] = pk2(v0.x, v0.x); xp[r][1] = pk2(v0.y, v0.y);
                xp[r][2] = pk2(v0.z, v0.z); xp[r][3] = pk2(v0.w, v0.w);
                xp[r][4] = pk2(v1.x, v1.x); xp[r][5] = pk2(v1.y, v1.y);
                xp[r][6] = pk2(v1.z, v1.z); xp[r][7] = pk2(v1.w, v1.w);
            }
            const unsigned long long* wp2 = ws2 + (icc * 32 + og) * 9;
#pragma unroll
            for (int ky = 0; ky < 3; ky++)
#pragma unroll
                for (int kx = 0; kx < 3; kx++) {
                    unsigned long long wv = wp2[ky * 3 + kx];
#pragma unroll
                    for (int ox = 0; ox < 6; ox++)
                        acc2[ox] = fma2(wv, xp[ky][ox + kx], acc2[ox]);
                }
        }
    }
    {
        int oc = og * 2;
#pragma unroll
        for (int ox = 0; ox < 6; ox++) {
            float a0, a1;
            upk2(acc2[ox], a0, a1);
            y0[oc * 36 + oy * 6 + ox]       = fmaxf(a0, 0.f);
            y0[(oc + 1) * 36 + oy * 6 + ox] = fmaxf(a1, 0.f);
        }
    }

    // --- conv1: 64ch 6x6 -> 64ch 4x4 (f32x2 over oc pair) ---------------
    const int oy1 = tid % 4;
    const int og1 = tid / 4;  // valid for tid<128
    unsigned long long bcc[4];
#pragma unroll
    for (int i = 0; i < 4; i++) bcc[i] = 0ull;

    for (int ch = 0; ch < 8; ch++) {
        const int ic0 = ch * 8;
        __syncthreads();
        for (int t = tid; t < 2304; t += 192) {
            int k = t % 9, rest = t / 9;
            int ogs = rest % 32, icc = rest / 32;
            int ic  = ic0 + icc;
            float wa = w1[(2 * ogs)     * 576 + ic * 9 + k];
            float wb = w1[(2 * ogs + 1) * 576 + ic * 9 + k];
            ws2[t] = pk2(wa, wb);
        }
        __syncthreads();
        if (tid < 128) {
            for (int icc = 0; icc < 8; icc++) {
                const float* xs = y0 + (ic0 + icc) * 36;
                unsigned long long xp[3][6];
#pragma unroll
                for (int r = 0; r < 3; r++) {
                    const float2 v0 = *reinterpret_cast<const float2*>(xs + (oy1 + r) * 6);
                    const float2 v1 = *reinterpret_cast<const float2*>(xs + (oy1 + r) * 6 + 2);
                    const float2 v2 = *reinterpret_cast<const float2*>(xs + (oy1 + r) * 6 + 4);
                    xp[r][0] = pk2(v0.x, v0.x); xp[r][1] = pk2(v0.y, v0.y);
                    xp[r][2] = pk2(v1.x, v1.x); xp[r][3] = pk2(v1.y, v1.y);
                    xp[r][4] = pk2(v2.x, v2.x); xp[r][5] = pk2(v2.y, v2.y);
                }
                const unsigned long long* wp2 = ws2 + (icc * 32 + og1) * 9;
#pragma unroll
                for (int ky = 0; ky < 3; ky++)
#pragma unroll
                    for (int kx = 0; kx < 3; kx++) {
                        unsigned long long wv = wp2[ky * 3 + kx];
#pragma unroll
                        for (int ox = 0; ox < 4; ox++)
                            bcc[ox] = fma2(wv, xp[ky][ox + kx], bcc[ox]);
                    }
            }
        }
    }
    if (tid < 128) {
        int oc = og1 * 2;
#pragma unroll
        for (int ox = 0; ox < 4; ox++) {
            float b0, b1;
            upk2(bcc[ox], b0, b1);
            y1[oc * 16 + oy1 * 4 + ox]       = fmaxf(b0, 0.f);
            y1[(oc + 1) * 16 + oy1 * 4 + ox] = fmaxf(b1, 0.f);
        }
    }

    // --- conv2: 64ch 4x4 -> 128ch 2x2 (scalar) ---------------------------
    float c2[4] = {0.f, 0.f, 0.f, 0.f};
    for (int ch = 0; ch < 16; ch++) {
        const int ic0 = ch * 4;
        __syncthreads();
        for (int t = tid; t < 4608; t += 192) {
            int icc = t / 1152, rem = t % 1152;
            int oc = rem / 9, k = rem % 9;
            ws[t] = w2[oc * 576 + (ic0 + icc) * 9 + k];
        }
        __syncthreads();
        if (tid < 128) {
            for (int icc = 0; icc < 4; icc++) {
                const float* xs = y1 + (ic0 + icc) * 16;
                float xr[16];
#pragma unroll
                for (int p = 0; p < 4; p++) {
                    const float4 v = *reinterpret_cast<const float4*>(xs + p * 4);
                    xr[p * 4 + 0] = v.x; xr[p * 4 + 1] = v.y;
                    xr[p * 4 + 2] = v.z; xr[p * 4 + 3] = v.w;
                }
                const float* wp = ws + icc * 1152 + tid * 9;
#pragma unroll
                for (int ky = 0; ky < 3; ky++)
#pragma unroll
                    for (int kx = 0; kx < 3; kx++) {
                        float wv = wp[ky * 3 + kx];
#pragma unroll
                        for (int oy2 = 0; oy2 < 2; oy2++)
#pragma unroll
                            for (int ox2 = 0; ox2 < 2; ox2++)
                                c2[oy2 * 2 + ox2] += xr[(oy2 + ky) * 4 + ox2 + kx] * wv;
                    }
            }
        }
    }
    if (tid < 128) {
#pragma unroll
        for (int p = 0; p < 4; p++) y2[tid * 4 + p] = fmaxf(c2[p], 0.f);
    }

    // --- conv3: 128ch 2x2 -> 128ch 1x1 (scalar) --------------------------
    float acc3 = 0.f;
    for (int ch = 0; ch < 16; ch++) {
        const int ic0 = ch * 8;
        __syncthreads();
        for (int t = tid; t < 4096; t += 192) {
            int icc = t >> 9, rem = t & 511;
            int oc = rem >> 2, k = rem & 3;
            ws[t] = w3[oc * 512 + (ic0 + icc) * 4 + k];
        }
        __syncthreads();
        if (tid < 128) {
            for (int icc = 0; icc < 8; icc++) {
                const float* xs = y2 + (ic0 + icc) * 4;
                const float* wp = ws + icc * 512 + tid * 4;
                acc3 += xs[0] * wp[0] + xs[1] * wp[1] + xs[2] * wp[2] + xs[3] * wp[3];
            }
        }
    }
    if (tid < 128) {
        out[OUT_NP + b * 131072 + tid * 1024 + s] = fmaxf(acc3, 0.f);
    }
}

// ---------------------------------------------------------------------------
extern "C" void kernel_launch(void* const* d_in, const int* in_sizes, int n_in,
                              void* d_out, int out_size)
{
    const float* xyz   = (const float*)d_in[0];
    const float* feats = (const float*)d_in[1];
    const float* w0    = (const float*)d_in[2];
    const float* w1    = (const float*)d_in[3];
    const float* w2    = (const float*)d_in[4];
    const float* w3    = (const float*)d_in[5];
    float* out = (float*)d_out;

    cudaFuncSetAttribute(fused_conv_kernel,
                         cudaFuncAttributeMaxDynamicSharedMemorySize,
                         SMEM_FLOATS * (int)sizeof(float));

    fps_kernel<<<NB, 1024>>>(xyz, out);
    knn_kernel<<<16, 128>>>();
    fused_conv_kernel<<<NB * NS, 192, SMEM_FLOATS * sizeof(float)>>>(
        feats, w0, w1, w2, w3, out);
}